// round 13
// baseline (speedup 1.0000x reference)
#include <cuda_runtime.h>
#include <cuda_bf16.h>
#include <cstdint>

#define BSZ  32
#define NUMS 512
#define FEAT 1024
#define NH   8
#define HLEN 128

#define NF ((size_t)BSZ * NUMS * FEAT)
// bf16 scratch (allocation-free rule: __device__ globals)
__device__ __nv_bfloat16 g_x1h[NF];                 // x1 bf16, [b,n,f]
__device__ __nv_bfloat16 g_Qh [NF];                 // Q*(gate^2*scale) bf16, [b,h,n,d]
__device__ __nv_bfloat16 g_Oh [NF];                 // att@V bf16, [b,n,f]
__device__ __nv_bfloat16 g_Wqh[FEAT * FEAT];        // [h,f,d] flat
__device__ __nv_bfloat16 g_Wlh[FEAT * FEAT];        // [f,n]
__device__ float g_gate2[BSZ * FEAT];
__device__ uint32_t g_mbits[BSZ * NUMS * (NUMS / 32)];   // packed mask bits

// ---------------------------------------------------------------- helpers
__device__ __forceinline__ uint32_t smem_u32(const void* p) {
    uint32_t a;
    asm("{ .reg .u64 t; cvta.to.shared.u64 t, %1; cvt.u32.u64 %0, t; }" : "=r"(a) : "l"(p));
    return a;
}
__device__ __forceinline__ uint32_t pack2(float a, float b) {
    __nv_bfloat162 t = __floats2bfloat162_rn(a, b);
    return *(uint32_t*)&t;
}
__device__ __forceinline__ void mma16816(float* c, const uint32_t* a, const uint32_t* b) {
    asm volatile(
        "mma.sync.aligned.m16n8k16.row.col.f32.bf16.bf16.f32 "
        "{%0,%1,%2,%3}, {%4,%5,%6,%7}, {%8,%9}, {%0,%1,%2,%3};"
        : "+f"(c[0]), "+f"(c[1]), "+f"(c[2]), "+f"(c[3])
        : "r"(a[0]), "r"(a[1]), "r"(a[2]), "r"(a[3]), "r"(b[0]), "r"(b[1]));
}
__device__ __forceinline__ void ldm_x4(uint32_t* r, uint32_t sa) {
    asm volatile("ldmatrix.sync.aligned.m8n8.x4.shared.b16 {%0,%1,%2,%3}, [%4];"
        : "=r"(r[0]), "=r"(r[1]), "=r"(r[2]), "=r"(r[3]) : "r"(sa));
}
__device__ __forceinline__ void ldm_x2(uint32_t* r, uint32_t sa) {
    asm volatile("ldmatrix.sync.aligned.m8n8.x2.shared.b16 {%0,%1}, [%2];"
        : "=r"(r[0]), "=r"(r[1]) : "r"(sa));
}
__device__ __forceinline__ void ldm_x4_t(uint32_t* r, uint32_t sa) {
    asm volatile("ldmatrix.sync.aligned.m8n8.x4.trans.shared.b16 {%0,%1,%2,%3}, [%4];"
        : "=r"(r[0]), "=r"(r[1]), "=r"(r[2]), "=r"(r[3]) : "r"(sa));
}
__device__ __forceinline__ void cpa16(uint32_t dst, const void* src) {
    asm volatile("cp.async.cg.shared.global [%0], [%1], 16;" :: "r"(dst), "l"(src));
}
#define CP_COMMIT() asm volatile("cp.async.commit_group;" ::: "memory")
#define CP_WAIT(n)  asm volatile("cp.async.wait_group %0;" :: "n"(n) : "memory")

// ---------------------------------------------------------------- convert to bf16
__global__ void cvt_h(const float* __restrict__ src, __nv_bfloat16* __restrict__ h, int n4) {
    int i = blockIdx.x * 256 + threadIdx.x;
    if (i < n4) {
        float4 v = ((const float4*)src)[i];
        ((uint2*)h)[i] = make_uint2(pack2(v.x, v.y), pack2(v.z, v.w));
    }
}

// ---------------------------------------------------------------- pack mask -> bits
__global__ void mask_pack(const unsigned* __restrict__ mask) {
    int t = blockIdx.x * 256 + threadIdx.x;
    unsigned v = mask[t];
    uint32_t w = __ballot_sync(0xffffffffu, v != 0);
    if ((t & 31) == 0) g_mbits[t >> 5] = w;
}

// ---------------------------------------------------------------- gate^2
__global__ void gate_kernel(const float* __restrict__ x2) {
    int b = blockIdx.y;
    int f = blockIdx.x * 256 + threadIdx.x;
    const float* p = x2 + (size_t)b * NUMS * FEAT + f;
    float s = 0.f;
#pragma unroll 8
    for (int n = 0; n < NUMS; n++) s += p[(size_t)n * FEAT];
    float g = s * (1.0f / NUMS);
    g_gate2[b * FEAT + f] = g * g * 0.08838834764831845f;  // 1/sqrt(128)
}

// ================================================================
// pipelined bf16 GEMM (unchanged, at mma.sync floor): k-chunk 64, 3 stages.
#define AELE 9216
#define BELE 8704
#define STAGE_E (AELE + BELE)
#define GEMM_SMEM (3 * STAGE_E * 2)         // 107520 B

template <int MODE>
__global__ void __launch_bounds__(512) gemm_mma(
    const float* __restrict__ bias, const float* __restrict__ res,
    float* __restrict__ Cout)
{
    extern __shared__ __nv_bfloat16 smb[];
    const uint32_t sb = smem_u32(smb);
    const int tid = threadIdx.x;
    const int n0 = blockIdx.x * 128;
    const int m0 = blockIdx.y * 128;
    const int wid = tid >> 5, lane = tid & 31;
    const int wm = (wid >> 2) * 32, wn = (wid & 3) * 32;
    const int g = lane >> 2, q = lane & 3;

    const __nv_bfloat16* Ahg = MODE ? g_Oh : g_x1h;
    const __nv_bfloat16* Bhg = MODE ? g_Wlh + n0 : g_Wqh + (size_t)(n0 >> 7) * FEAT * HLEN;
    const int ldbn = MODE ? FEAT : HLEN;

    const int ar = tid >> 2, ac = (tid & 3) * 16;
    const int br = tid >> 3, bc = (tid & 7) * 16;
    const size_t aoff = (size_t)(m0 + ar) * FEAT + ac;

    auto issue = [&](int slot, int k0) {
        uint32_t s = sb + slot * STAGE_E * 2;
        const __nv_bfloat16* ap = Ahg + aoff + k0;
        uint32_t da = s + (ar * 72 + ac) * 2;
        cpa16(da,      ap);
        cpa16(da + 16, ap + 8);
        const __nv_bfloat16* bp = Bhg + (size_t)(k0 + br) * ldbn + bc;
        uint32_t db = s + AELE * 2 + (br * 136 + bc) * 2;
        cpa16(db,      bp);
        cpa16(db + 16, bp + 8);
        CP_COMMIT();
    };

    float c[2][4][4];
#pragma unroll
    for (int i = 0; i < 2; i++)
#pragma unroll
        for (int j = 0; j < 4; j++)
#pragma unroll
            for (int k = 0; k < 4; k++) c[i][j][k] = 0.f;

    const uint32_t lnA = ((lane & 15) * 72 + (lane >> 4) * 8) * 2;
    const uint32_t lnB = ((lane & 15) * 136 + (lane >> 4) * 8) * 2;

    issue(0, 0);
    issue(1, 64);

    for (int ch = 0; ch < 16; ch++) {
        if (ch < 15) { CP_WAIT(1); } else { CP_WAIT(0); }
        __syncthreads();
        if (ch + 2 <= 15) issue((ch + 2) % 3, (ch + 2) * 64);

        uint32_t sA = sb + (ch % 3) * STAGE_E * 2;
        uint32_t sB = sA + AELE * 2;
#pragma unroll
        for (int ks = 0; ks < 4; ks++) {
            uint32_t ah[2][4];
#pragma unroll
            for (int mt = 0; mt < 2; mt++)
                ldm_x4(ah[mt], sA + ((wm + mt * 16) * 72 + ks * 16) * 2 + lnA);
            uint32_t bfh[2][4];
#pragma unroll
            for (int bg = 0; bg < 2; bg++)
                ldm_x4_t(bfh[bg], sB + (ks * 16 * 136 + wn + bg * 16) * 2 + lnB);
#pragma unroll
            for (int mt = 0; mt < 2; mt++)
#pragma unroll
                for (int nt = 0; nt < 4; nt++)
                    mma16816(c[mt][nt], ah[mt], &bfh[nt >> 1][(nt & 1) * 2]);
        }
    }

#pragma unroll
    for (int mt = 0; mt < 2; mt++)
#pragma unroll
        for (int nt = 0; nt < 4; nt++) {
            const int dcol = wn + nt * 8 + q * 2;
            const int col = n0 + dcol;
#pragma unroll
            for (int hh = 0; hh < 2; hh++) {
                const int m = m0 + wm + mt * 16 + g + hh * 8;
                float v0 = c[mt][nt][hh * 2 + 0];
                float v1 = c[mt][nt][hh * 2 + 1];
                if (MODE == 0) {
                    const int bi = m >> 9, ns = m & 511, h = n0 >> 7;
                    v0 = (v0 + bias[col])     * g_gate2[bi * FEAT + col];
                    v1 = (v1 + bias[col + 1]) * g_gate2[bi * FEAT + col + 1];
                    size_t o = (((size_t)bi * NH + h) * NUMS + ns) * HLEN + dcol;
                    *(uint32_t*)&g_Qh[o] = pack2(v0, v1);
                } else {
                    float2 o;
                    o.x = fmaxf(v0 + bias[col], 0.f)     + res[(size_t)m * FEAT + col];
                    o.y = fmaxf(v1 + bias[col + 1], 0.f) + res[(size_t)m * FEAT + col + 1];
                    *(float2*)&Cout[(size_t)m * FEAT + col] = o;
                }
            }
        }
}

// ================================================================
// attention: 32 Q-rows/CTA -> 96256 B smem -> 2 CTAs/SM.
// smem: Q[32][136] @0 (8704); P[32][520] @8704 (33280);
//       KV 3 slots @41984 (3x17408=52224); red @94208 (2048).
#define QOFF 0
#define POFF 8704
#define KVOFF 41984
#define REDOFF 94208
#define ATT_SMEM 96256
__global__ void __launch_bounds__(512) attn_mma(float* __restrict__ att_out)
{
    extern __shared__ char smc[];
    const uint32_t sb = smem_u32(smc);
    float* red = (float*)(smc + REDOFF);
    const int tid = threadIdx.x;
    const int wid = tid >> 5, lane = tid & 31;
    const int g = lane >> 2, q = lane & 3;
    const int n0 = blockIdx.x * 32;
    const int h = blockIdx.y, b = blockIdx.z;

    const uint32_t lnB = ((lane & 15) * 136 + (lane >> 4) * 8) * 2;  // x4, stride 136
    const uint32_t lnQ = ((lane & 15) * 136 + (lane >> 4) * 8) * 2;
    const uint32_t lnP = ((lane & 15) * 520 + (lane >> 4) * 8) * 2;
    const uint32_t KVB = sb + KVOFF;
    const uint32_t PB  = sb + POFF;

    auto issueKV = [&](int ck, int slot) {
        const int row = tid >> 3, cb = (tid & 7) * 16;
        size_t so = ((size_t)b * NUMS + ck * 64 + row) * FEAT + h * HLEN + cb;
        uint32_t d = KVB + slot * 17408 + (row * 136 + cb) * 2;
        cpa16(d,      g_x1h + so);
        cpa16(d + 16, g_x1h + so + 8);
        CP_COMMIT();
    };

    // ---- prologue: Q (32 rows), K chunks 0,1
    {
        const int row = tid >> 4, cb = (tid & 15) * 8;   // 32 rows x 16 8-col pieces
        size_t so = (((size_t)b * NH + h) * NUMS + n0 + row) * HLEN + cb;
        cpa16(sb + QOFF + (row * 136 + cb) * 2, g_Qh + so);
        CP_COMMIT();
    }
    issueKV(0, 0);
    issueKV(1, 1);

    // warp layout phase 1: rm = (wid>>3)*16 (2 m-groups), cn = (wid&7)*8 (8 n-slots)
    const int rm = (wid >> 3) * 16, cn = (wid & 7) * 8;
    const int wn_idx = wid & 7;
    const int r0 = rm + g, r1 = r0 + 8;
    const uint32_t* mb0 = g_mbits + ((size_t)b * NUMS + n0 + r0) * (NUMS / 32);
    const uint32_t* mb1 = g_mbits + ((size_t)b * NUMS + n0 + r1) * (NUMS / 32);
    // x2 K-frag address: lanes 0-7 -> n-row cn+l @k0; 8-15 -> cn+l @k+8
    const uint32_t lnK = (((lane & 7) + cn) * 136 + ((lane >> 3) & 1) * 8) * 2;

    CP_WAIT(1);            // Q + K0 resident
    __syncthreads();

    // hoist Q fragments (rows rm..rm+15, all k)
    uint32_t qf[8][4];
#pragma unroll
    for (int ks = 0; ks < 8; ks++)
        ldm_x4(qf[ks], sb + QOFF + (rm * 136 + ks * 16) * 2 + lnQ);

    float cA[8][4];

    // ---- phase 1: S = Q K^T, 8 chunks of 64 keys (warp: m16 x n8)
#pragma unroll
    for (int ck = 0; ck < 8; ck++) {
        if (ck > 0) {
            if (ck < 7) { CP_WAIT(1); } else { CP_WAIT(0); }
            __syncthreads();
        }
        if (ck + 2 <= 7) issueKV(ck + 2, (ck + 2) % 3);

        uint32_t kbh = KVB + (ck % 3) * 17408;
        float* c1 = cA[ck];
#pragma unroll
        for (int k = 0; k < 4; k++) c1[k] = 0.f;
#pragma unroll
        for (int ks = 0; ks < 8; ks++) {
            uint32_t kh[2];
            ldm_x2(kh, kbh + (ks * 16) * 2 + lnK);
            mma16816(c1, qf[ks], kh);
        }
        // fold mask bits
        const int col = ck * 64 + cn + q * 2;
        uint32_t w0 = (mb0[col >> 5] >> (col & 31)) & 3u;
        uint32_t w1 = (mb1[col >> 5] >> (col & 31)) & 3u;
        if (w0 & 1u) c1[0] = -1e9f;
        if (w0 & 2u) c1[1] = -1e9f;
        if (w1 & 1u) c1[2] = -1e9f;
        if (w1 & 2u) c1[3] = -1e9f;
    }

    // ---- phase 2: register softmax (quad shfl + 8-warp smem reduce)
    float mx0 = -1e30f, mx1 = -1e30f;
#pragma unroll
    for (int ck = 0; ck < 8; ck++) {
        mx0 = fmaxf(mx0, fmaxf(cA[ck][0], cA[ck][1]));
        mx1 = fmaxf(mx1, fmaxf(cA[ck][2], cA[ck][3]));
    }
    mx0 = fmaxf(mx0, __shfl_xor_sync(0xffffffffu, mx0, 1));
    mx0 = fmaxf(mx0, __shfl_xor_sync(0xffffffffu, mx0, 2));
    mx1 = fmaxf(mx1, __shfl_xor_sync(0xffffffffu, mx1, 1));
    mx1 = fmaxf(mx1, __shfl_xor_sync(0xffffffffu, mx1, 2));
    if (q == 0) {
        red[r0 * 8 + wn_idx] = mx0;
        red[r1 * 8 + wn_idx] = mx1;
    }
    __syncthreads();          // red ready; also all K-slot reads done
    issueKV(0, 0);            // prefetch V chunks over softmax
    issueKV(1, 1);
    mx0 = red[r0 * 8 + 0]; mx1 = red[r1 * 8 + 0];
#pragma unroll
    for (int i = 1; i < 8; i++) {
        mx0 = fmaxf(mx0, red[r0 * 8 + i]);
        mx1 = fmaxf(mx1, red[r1 * 8 + i]);
    }

    float s0 = 0.f, s1 = 0.f;
#pragma unroll
    for (int ck = 0; ck < 8; ck++) {
        float e0 = __expf(cA[ck][0] - mx0);
        float e1 = __expf(cA[ck][1] - mx0);
        float e2 = __expf(cA[ck][2] - mx1);
        float e3 = __expf(cA[ck][3] - mx1);
        cA[ck][0] = e0; cA[ck][1] = e1; cA[ck][2] = e2; cA[ck][3] = e3;
        s0 += e0 + e1; s1 += e2 + e3;
    }
    s0 += __shfl_xor_sync(0xffffffffu, s0, 1);
    s0 += __shfl_xor_sync(0xffffffffu, s0, 2);
    s1 += __shfl_xor_sync(0xffffffffu, s1, 1);
    s1 += __shfl_xor_sync(0xffffffffu, s1, 2);
    if (q == 0) {
        red[256 + r0 * 8 + wn_idx] = s0;
        red[256 + r1 * 8 + wn_idx] = s1;
    }
    __syncthreads();
    s0 = 0.f; s1 = 0.f;
#pragma unroll
    for (int i = 0; i < 8; i++) {
        s0 += red[256 + r0 * 8 + i];
        s1 += red[256 + r1 * 8 + i];
    }
    float inv0 = 1.0f / s0, inv1 = 1.0f / s1;

    // write att (fp32, streaming) + P (bf16, smem)
    float* arow0 = att_out + (((size_t)b * NH + h) * NUMS + (n0 + r0)) * NUMS;
    float* arow1 = att_out + (((size_t)b * NH + h) * NUMS + (n0 + r1)) * NUMS;
#pragma unroll
    for (int ck = 0; ck < 8; ck++) {
        const int col = ck * 64 + cn + q * 2;
        float p0 = cA[ck][0] * inv0, p1 = cA[ck][1] * inv0;
        float p2 = cA[ck][2] * inv1, p3 = cA[ck][3] * inv1;
        __stcs((float2*)&arow0[col], make_float2(p0, p1));
        __stcs((float2*)&arow1[col], make_float2(p2, p3));
        *(uint32_t*)(smc + POFF + (r0 * 520 + col) * 2) = pack2(p0, p1);
        *(uint32_t*)(smc + POFF + (r1 * 520 + col) * 2) = pack2(p2, p3);
    }
    __syncthreads();          // P complete

    // ---- phase 3: O = att @ V, 8 chunks; warp: m16 x d16
    const int wm3 = (wid >> 3) * 16, wn3 = (wid & 7) * 16;
    float c3[2][4];
#pragma unroll
    for (int i = 0; i < 2; i++)
#pragma unroll
        for (int k = 0; k < 4; k++) c3[i][k] = 0.f;

    for (int kt = 0; kt < 8; kt++) {
        if (kt < 7) { CP_WAIT(1); } else { CP_WAIT(0); }
        __syncthreads();
        if (kt + 2 <= 7) issueKV(kt + 2, (kt + 2) % 3);

        uint32_t vbh = KVB + (kt % 3) * 17408;
#pragma unroll
        for (int ks = 0; ks < 4; ks++) {
            uint32_t ph[4];
            ldm_x4(ph, PB + (wm3 * 520 + kt * 64 + ks * 16) * 2 + lnP);
            uint32_t vh[4];
            ldm_x4_t(vh, vbh + (ks * 16 * 136 + wn3) * 2 + lnB);
            mma16816(c3[0], ph, &vh[0]);
            mma16816(c3[1], ph, &vh[2]);
        }
    }

    // ---- epilogue: O -> g_Oh [b, n, f] (bf16)
#pragma unroll
    for (int hf = 0; hf < 2; hf++) {
        const float* cc = c3[hf];
        const int d = wn3 + hf * 8 + q * 2;
        const int row = wm3 + g;
        size_t o0 = ((size_t)b * NUMS + n0 + row) * FEAT + h * HLEN + d;
        size_t o1 = o0 + 8 * FEAT;
        *(uint32_t*)&g_Oh[o0] = pack2(cc[0], cc[1]);
        *(uint32_t*)&g_Oh[o1] = pack2(cc[2], cc[3]);
    }
}

// ----------------------------------------------------------------
extern "C" void kernel_launch(void* const* d_in, const int* in_sizes, int n_in,
                              void* d_out, int out_size) {
    const float*    x1   = (const float*)d_in[0];
    const float*    x2   = (const float*)d_in[1];
    const unsigned* mask = (const unsigned*)d_in[4];
    const float*    Wq   = (const float*)d_in[5];
    const float*    bq   = (const float*)d_in[6];
    const float*    Wl   = (const float*)d_in[7];
    const float*    bl   = (const float*)d_in[8];
    float* out = (float*)d_out;
    float* att = out + (size_t)BSZ * NUMS * FEAT;   // tuple: (xout, att)

    dim3 gg(FEAT / 256, BSZ);
    gate_kernel<<<gg, 256>>>(x2);

    { void* p; cudaGetSymbolAddress(&p, g_x1h);
      cvt_h<<<(int)(NF / 4 / 256), 256>>>(x1, (__nv_bfloat16*)p, (int)(NF / 4)); }
    { void* p; cudaGetSymbolAddress(&p, g_Wqh);
      cvt_h<<<FEAT * FEAT / 4 / 256, 256>>>(Wq, (__nv_bfloat16*)p, FEAT * FEAT / 4); }
    { void* p; cudaGetSymbolAddress(&p, g_Wlh);
      cvt_h<<<FEAT * FEAT / 4 / 256, 256>>>(Wl, (__nv_bfloat16*)p, FEAT * FEAT / 4); }

    mask_pack<<<BSZ * NUMS * NUMS / 256, 256>>>(mask);

    cudaFuncSetAttribute(gemm_mma<0>, cudaFuncAttributeMaxDynamicSharedMemorySize, GEMM_SMEM);
    cudaFuncSetAttribute(gemm_mma<1>, cudaFuncAttributeMaxDynamicSharedMemorySize, GEMM_SMEM);
    cudaFuncSetAttribute(attn_mma,    cudaFuncAttributeMaxDynamicSharedMemorySize, ATT_SMEM);

    dim3 ggemm(FEAT / 128, (BSZ * NUMS) / 128);
    gemm_mma<0><<<ggemm, 512, GEMM_SMEM>>>(bq, nullptr, nullptr);

    dim3 ga(NUMS / 32, NH, BSZ);
    attn_mma<<<ga, 512, ATT_SMEM>>>(att);

    gemm_mma<1><<<ggemm, 512, GEMM_SMEM>>>(bl, x1, out);
}

// round 14
// speedup vs baseline: 1.0531x; 1.0531x over previous
#include <cuda_runtime.h>
#include <cuda_bf16.h>
#include <cstdint>

#define BSZ  32
#define NUMS 512
#define FEAT 1024
#define NH   8
#define HLEN 128

#define NF ((size_t)BSZ * NUMS * FEAT)
// bf16 scratch (allocation-free rule: __device__ globals)
__device__ __nv_bfloat16 g_x1h[NF];                 // x1 bf16, [b,n,f]
__device__ __nv_bfloat16 g_Qh [NF];                 // Q*(gate^2*scale) bf16, [b,h,n,d]
__device__ __nv_bfloat16 g_Oh [NF];                 // att@V bf16, [b,n,f]
__device__ __nv_bfloat16 g_Wqh[FEAT * FEAT];        // [h,f,d] flat
__device__ __nv_bfloat16 g_Wlh[FEAT * FEAT];        // [f,n]
__device__ __nv_bfloat16 g_attb[(size_t)BSZ * NH * NUMS * NUMS];  // att bf16 copy
__device__ float g_gate2[BSZ * FEAT];
__device__ uint32_t g_mbits[BSZ * NUMS * (NUMS / 32)];   // packed mask bits

// ---------------------------------------------------------------- helpers
__device__ __forceinline__ uint32_t smem_u32(const void* p) {
    uint32_t a;
    asm("{ .reg .u64 t; cvta.to.shared.u64 t, %1; cvt.u32.u64 %0, t; }" : "=r"(a) : "l"(p));
    return a;
}
__device__ __forceinline__ uint32_t pack2(float a, float b) {
    __nv_bfloat162 t = __floats2bfloat162_rn(a, b);
    return *(uint32_t*)&t;
}
__device__ __forceinline__ void mma16816(float* c, const uint32_t* a, const uint32_t* b) {
    asm volatile(
        "mma.sync.aligned.m16n8k16.row.col.f32.bf16.bf16.f32 "
        "{%0,%1,%2,%3}, {%4,%5,%6,%7}, {%8,%9}, {%0,%1,%2,%3};"
        : "+f"(c[0]), "+f"(c[1]), "+f"(c[2]), "+f"(c[3])
        : "r"(a[0]), "r"(a[1]), "r"(a[2]), "r"(a[3]), "r"(b[0]), "r"(b[1]));
}
__device__ __forceinline__ void ldm_x4(uint32_t* r, uint32_t sa) {
    asm volatile("ldmatrix.sync.aligned.m8n8.x4.shared.b16 {%0,%1,%2,%3}, [%4];"
        : "=r"(r[0]), "=r"(r[1]), "=r"(r[2]), "=r"(r[3]) : "r"(sa));
}
__device__ __forceinline__ void ldm_x4_t(uint32_t* r, uint32_t sa) {
    asm volatile("ldmatrix.sync.aligned.m8n8.x4.trans.shared.b16 {%0,%1,%2,%3}, [%4];"
        : "=r"(r[0]), "=r"(r[1]), "=r"(r[2]), "=r"(r[3]) : "r"(sa));
}
__device__ __forceinline__ void cpa16(uint32_t dst, const void* src) {
    asm volatile("cp.async.cg.shared.global [%0], [%1], 16;" :: "r"(dst), "l"(src));
}
#define CP_COMMIT() asm volatile("cp.async.commit_group;" ::: "memory")
#define CP_WAIT(n)  asm volatile("cp.async.wait_group %0;" :: "n"(n) : "memory")

// ---------------------------------------------------------------- convert to bf16
__global__ void cvt_h(const float* __restrict__ src, __nv_bfloat16* __restrict__ h, int n4) {
    int i = blockIdx.x * 256 + threadIdx.x;
    if (i < n4) {
        float4 v = ((const float4*)src)[i];
        ((uint2*)h)[i] = make_uint2(pack2(v.x, v.y), pack2(v.z, v.w));
    }
}

// ---------------------------------------------------------------- pack mask -> bits
__global__ void mask_pack(const unsigned* __restrict__ mask) {
    int t = blockIdx.x * 256 + threadIdx.x;
    unsigned v = mask[t];
    uint32_t w = __ballot_sync(0xffffffffu, v != 0);
    if ((t & 31) == 0) g_mbits[t >> 5] = w;
}

// ---------------------------------------------------------------- gate^2
__global__ void gate_kernel(const float* __restrict__ x2) {
    int b = blockIdx.y;
    int f = blockIdx.x * 256 + threadIdx.x;
    const float* p = x2 + (size_t)b * NUMS * FEAT + f;
    float s = 0.f;
#pragma unroll 8
    for (int n = 0; n < NUMS; n++) s += p[(size_t)n * FEAT];
    float g = s * (1.0f / NUMS);
    g_gate2[b * FEAT + f] = g * g * 0.08838834764831845f;  // 1/sqrt(128)
}

// ================================================================
// pipelined bf16 GEMM (at mma.sync floor): k-chunk 64, 3 stages.
#define AELE 9216
#define BELE 8704
#define STAGE_E (AELE + BELE)
#define GEMM_SMEM (3 * STAGE_E * 2)         // 107520 B

template <int MODE>
__global__ void __launch_bounds__(512) gemm_mma(
    const float* __restrict__ bias, const float* __restrict__ res,
    float* __restrict__ Cout)
{
    extern __shared__ __nv_bfloat16 smb[];
    const uint32_t sb = smem_u32(smb);
    const int tid = threadIdx.x;
    const int n0 = blockIdx.x * 128;
    const int m0 = blockIdx.y * 128;
    const int wid = tid >> 5, lane = tid & 31;
    const int wm = (wid >> 2) * 32, wn = (wid & 3) * 32;
    const int g = lane >> 2, q = lane & 3;

    const __nv_bfloat16* Ahg = MODE ? g_Oh : g_x1h;
    const __nv_bfloat16* Bhg = MODE ? g_Wlh + n0 : g_Wqh + (size_t)(n0 >> 7) * FEAT * HLEN;
    const int ldbn = MODE ? FEAT : HLEN;

    const int ar = tid >> 2, ac = (tid & 3) * 16;
    const int br = tid >> 3, bc = (tid & 7) * 16;
    const size_t aoff = (size_t)(m0 + ar) * FEAT + ac;

    auto issue = [&](int slot, int k0) {
        uint32_t s = sb + slot * STAGE_E * 2;
        const __nv_bfloat16* ap = Ahg + aoff + k0;
        uint32_t da = s + (ar * 72 + ac) * 2;
        cpa16(da,      ap);
        cpa16(da + 16, ap + 8);
        const __nv_bfloat16* bp = Bhg + (size_t)(k0 + br) * ldbn + bc;
        uint32_t db = s + AELE * 2 + (br * 136 + bc) * 2;
        cpa16(db,      bp);
        cpa16(db + 16, bp + 8);
        CP_COMMIT();
    };

    float c[2][4][4];
#pragma unroll
    for (int i = 0; i < 2; i++)
#pragma unroll
        for (int j = 0; j < 4; j++)
#pragma unroll
            for (int k = 0; k < 4; k++) c[i][j][k] = 0.f;

    const uint32_t lnA = ((lane & 15) * 72 + (lane >> 4) * 8) * 2;
    const uint32_t lnB = ((lane & 15) * 136 + (lane >> 4) * 8) * 2;

    issue(0, 0);
    issue(1, 64);

    for (int ch = 0; ch < 16; ch++) {
        if (ch < 15) { CP_WAIT(1); } else { CP_WAIT(0); }
        __syncthreads();
        if (ch + 2 <= 15) issue((ch + 2) % 3, (ch + 2) * 64);

        uint32_t sA = sb + (ch % 3) * STAGE_E * 2;
        uint32_t sB = sA + AELE * 2;
#pragma unroll
        for (int ks = 0; ks < 4; ks++) {
            uint32_t ah[2][4];
#pragma unroll
            for (int mt = 0; mt < 2; mt++)
                ldm_x4(ah[mt], sA + ((wm + mt * 16) * 72 + ks * 16) * 2 + lnA);
            uint32_t bfh[2][4];
#pragma unroll
            for (int bg = 0; bg < 2; bg++)
                ldm_x4_t(bfh[bg], sB + (ks * 16 * 136 + wn + bg * 16) * 2 + lnB);
#pragma unroll
            for (int mt = 0; mt < 2; mt++)
#pragma unroll
                for (int nt = 0; nt < 4; nt++)
                    mma16816(c[mt][nt], ah[mt], &bfh[nt >> 1][(nt & 1) * 2]);
        }
    }

#pragma unroll
    for (int mt = 0; mt < 2; mt++)
#pragma unroll
        for (int nt = 0; nt < 4; nt++) {
            const int dcol = wn + nt * 8 + q * 2;
            const int col = n0 + dcol;
#pragma unroll
            for (int hh = 0; hh < 2; hh++) {
                const int m = m0 + wm + mt * 16 + g + hh * 8;
                float v0 = c[mt][nt][hh * 2 + 0];
                float v1 = c[mt][nt][hh * 2 + 1];
                if (MODE == 0) {
                    const int bi = m >> 9, ns = m & 511, h = n0 >> 7;
                    v0 = (v0 + bias[col])     * g_gate2[bi * FEAT + col];
                    v1 = (v1 + bias[col + 1]) * g_gate2[bi * FEAT + col + 1];
                    size_t o = (((size_t)bi * NH + h) * NUMS + ns) * HLEN + dcol;
                    *(uint32_t*)&g_Qh[o] = pack2(v0, v1);
                } else {
                    float2 o;
                    o.x = fmaxf(v0 + bias[col], 0.f)     + res[(size_t)m * FEAT + col];
                    o.y = fmaxf(v1 + bias[col + 1], 0.f) + res[(size_t)m * FEAT + col + 1];
                    *(float2*)&Cout[(size_t)m * FEAT + col] = o;
                }
            }
        }
}

// ================================================================
// gemm_av: O[n=512, d=128] = att_bf16[512x512] @ V[512x128] per (b,h).
// Same pipelined structure; A = g_attb (lda=512), B = x1h head slice.
__global__ void __launch_bounds__(512) gemm_av()
{
    extern __shared__ __nv_bfloat16 smb[];
    const uint32_t sb = smem_u32(smb);
    const int tid = threadIdx.x;
    const int m0 = blockIdx.x * 128;          // att row tile
    const int h = blockIdx.y, b = blockIdx.z;
    const int wid = tid >> 5, lane = tid & 31;
    const int wm = (wid >> 2) * 32, wn = (wid & 3) * 32;
    const int g = lane >> 2, q = lane & 3;

    const __nv_bfloat16* Ahg = g_attb + (((size_t)b * NH + h) * NUMS + m0) * NUMS;
    const __nv_bfloat16* Bhg = g_x1h + (size_t)b * NUMS * FEAT + h * HLEN;

    const int ar = tid >> 2, ac = (tid & 3) * 16;
    const int br = tid >> 3, bc = (tid & 7) * 16;

    auto issue = [&](int slot, int k0) {
        uint32_t s = sb + slot * STAGE_E * 2;
        const __nv_bfloat16* ap = Ahg + (size_t)ar * NUMS + k0 + ac;
        uint32_t da = s + (ar * 72 + ac) * 2;
        cpa16(da,      ap);
        cpa16(da + 16, ap + 8);
        const __nv_bfloat16* bp = Bhg + (size_t)(k0 + br) * FEAT + bc;
        uint32_t db = s + AELE * 2 + (br * 136 + bc) * 2;
        cpa16(db,      bp);
        cpa16(db + 16, bp + 8);
        CP_COMMIT();
    };

    float c[2][4][4];
#pragma unroll
    for (int i = 0; i < 2; i++)
#pragma unroll
        for (int j = 0; j < 4; j++)
#pragma unroll
            for (int k = 0; k < 4; k++) c[i][j][k] = 0.f;

    const uint32_t lnA = ((lane & 15) * 72 + (lane >> 4) * 8) * 2;
    const uint32_t lnB = ((lane & 15) * 136 + (lane >> 4) * 8) * 2;

    issue(0, 0);
    issue(1, 64);

    for (int ch = 0; ch < 8; ch++) {
        if (ch < 7) { CP_WAIT(1); } else { CP_WAIT(0); }
        __syncthreads();
        if (ch + 2 <= 7) issue((ch + 2) % 3, (ch + 2) * 64);

        uint32_t sA = sb + (ch % 3) * STAGE_E * 2;
        uint32_t sB = sA + AELE * 2;
#pragma unroll
        for (int ks = 0; ks < 4; ks++) {
            uint32_t ah[2][4];
#pragma unroll
            for (int mt = 0; mt < 2; mt++)
                ldm_x4(ah[mt], sA + ((wm + mt * 16) * 72 + ks * 16) * 2 + lnA);
            uint32_t bfh[2][4];
#pragma unroll
            for (int bg = 0; bg < 2; bg++)
                ldm_x4_t(bfh[bg], sB + (ks * 16 * 136 + wn + bg * 16) * 2 + lnB);
#pragma unroll
            for (int mt = 0; mt < 2; mt++)
#pragma unroll
                for (int nt = 0; nt < 4; nt++)
                    mma16816(c[mt][nt], ah[mt], &bfh[nt >> 1][(nt & 1) * 2]);
        }
    }

    // epilogue: O -> g_Oh[b, n0+m, h*128+d] bf16
#pragma unroll
    for (int mt = 0; mt < 2; mt++)
#pragma unroll
        for (int nt = 0; nt < 4; nt++) {
            const int dcol = wn + nt * 8 + q * 2;
#pragma unroll
            for (int hh = 0; hh < 2; hh++) {
                const int m = m0 + wm + mt * 16 + g + hh * 8;
                size_t o = ((size_t)b * NUMS + m) * FEAT + h * HLEN + dcol;
                *(uint32_t*)&g_Oh[o] = pack2(c[mt][nt][hh * 2 + 0], c[mt][nt][hh * 2 + 1]);
            }
        }
}

// ================================================================
// attn_s: S = QK^T + mask + register softmax; writes att fp32 + att bf16.
// smem: Q[64][136] @0 (17408); K 8 slots @17408 (139264); red @156672 (2048).
#define QOFF 0
#define KVOFF 17408
#define REDOFF 156672
#define ATT_SMEM 158720
__global__ void __launch_bounds__(512) attn_s(float* __restrict__ att_out)
{
    extern __shared__ char smc[];
    const uint32_t sb = smem_u32(smc);
    float* red = (float*)(smc + REDOFF);
    const int tid = threadIdx.x;
    const int wid = tid >> 5, lane = tid & 31;
    const int g = lane >> 2, q = lane & 3;
    const int n0 = blockIdx.x * 64;
    const int h = blockIdx.y, b = blockIdx.z;

    const uint32_t lnB = ((lane & 15) * 136 + (lane >> 4) * 8) * 2;
    const uint32_t KVB = sb + KVOFF;

    auto issueKV = [&](int ck) {
        const int row = tid >> 3, cb = (tid & 7) * 16;
        size_t so = ((size_t)b * NUMS + ck * 64 + row) * FEAT + h * HLEN + cb;
        uint32_t d = KVB + ck * 17408 + (row * 136 + cb) * 2;
        cpa16(d,      g_x1h + so);
        cpa16(d + 16, g_x1h + so + 8);
        CP_COMMIT();
    };

    // ---- prologue: Q, K chunks 0,1
    {
        const int row = tid >> 3, cb = (tid & 7) * 16;
        size_t so = (((size_t)b * NH + h) * NUMS + n0 + row) * HLEN + cb;
        uint32_t d = sb + QOFF + (row * 136 + cb) * 2;
        cpa16(d,      g_Qh + so);
        cpa16(d + 16, g_Qh + so + 8);
        CP_COMMIT();
    }
    issueKV(0);
    issueKV(1);

    const int wm2 = (wid >> 2) * 16, wn2 = (wid & 3) * 16;
    const int r0 = wm2 + g, r1 = r0 + 8;
    const uint32_t* mb0 = g_mbits + ((size_t)b * NUMS + n0 + r0) * (NUMS / 32);
    const uint32_t* mb1 = g_mbits + ((size_t)b * NUMS + n0 + r1) * (NUMS / 32);

    float cA[8][2][4];

    // ---- phase 1: S = Q K^T, 8 chunks into distinct slots
#pragma unroll
    for (int ck = 0; ck < 8; ck++) {
        CP_WAIT(1);
        __syncthreads();
        if (ck + 2 <= 7) issueKV(ck + 2);

        uint32_t kbh = KVB + ck * 17408;
        float* c0 = cA[ck][0];
        float* c1 = cA[ck][1];
#pragma unroll
        for (int k = 0; k < 4; k++) { c0[k] = 0.f; c1[k] = 0.f; }
#pragma unroll
        for (int ks = 0; ks < 8; ks++) {
            uint32_t qf[4], kh[4];
            ldm_x4(qf, sb + QOFF + (wm2 * 136 + ks * 16) * 2 + lnB);
            ldm_x4(kh, kbh + (wn2 * 136 + ks * 16) * 2 + lnB);
            uint32_t b0h[2] = {kh[0], kh[2]}, b1h[2] = {kh[1], kh[3]};
            mma16816(c0, qf, b0h);
            mma16816(c1, qf, b1h);
        }
#pragma unroll
        for (int nt = 0; nt < 2; nt++) {
            const int col = ck * 64 + wn2 + nt * 8 + q * 2;
            uint32_t w0 = (mb0[col >> 5] >> (col & 31)) & 3u;
            uint32_t w1 = (mb1[col >> 5] >> (col & 31)) & 3u;
            if (w0 & 1u) cA[ck][nt][0] = -1e9f;
            if (w0 & 2u) cA[ck][nt][1] = -1e9f;
            if (w1 & 1u) cA[ck][nt][2] = -1e9f;
            if (w1 & 2u) cA[ck][nt][3] = -1e9f;
        }
    }

    // ---- phase 2: register softmax
    float mx0 = -1e30f, mx1 = -1e30f;
#pragma unroll
    for (int ck = 0; ck < 8; ck++)
#pragma unroll
        for (int nt = 0; nt < 2; nt++) {
            mx0 = fmaxf(mx0, fmaxf(cA[ck][nt][0], cA[ck][nt][1]));
            mx1 = fmaxf(mx1, fmaxf(cA[ck][nt][2], cA[ck][nt][3]));
        }
    mx0 = fmaxf(mx0, __shfl_xor_sync(0xffffffffu, mx0, 1));
    mx0 = fmaxf(mx0, __shfl_xor_sync(0xffffffffu, mx0, 2));
    mx1 = fmaxf(mx1, __shfl_xor_sync(0xffffffffu, mx1, 1));
    mx1 = fmaxf(mx1, __shfl_xor_sync(0xffffffffu, mx1, 2));
    if (q == 0) {
        red[r0 * 4 + (wid & 3)] = mx0;
        red[r1 * 4 + (wid & 3)] = mx1;
    }
    __syncthreads();
    mx0 = fmaxf(fmaxf(red[r0 * 4 + 0], red[r0 * 4 + 1]),
                fmaxf(red[r0 * 4 + 2], red[r0 * 4 + 3]));
    mx1 = fmaxf(fmaxf(red[r1 * 4 + 0], red[r1 * 4 + 1]),
                fmaxf(red[r1 * 4 + 2], red[r1 * 4 + 3]));

    float s0 = 0.f, s1 = 0.f;
#pragma unroll
    for (int ck = 0; ck < 8; ck++)
#pragma unroll
        for (int nt = 0; nt < 2; nt++) {
            float e0 = __expf(cA[ck][nt][0] - mx0);
            float e1 = __expf(cA[ck][nt][1] - mx0);
            float e2 = __expf(cA[ck][nt][2] - mx1);
            float e3 = __expf(cA[ck][nt][3] - mx1);
            cA[ck][nt][0] = e0; cA[ck][nt][1] = e1;
            cA[ck][nt][2] = e2; cA[ck][nt][3] = e3;
            s0 += e0 + e1; s1 += e2 + e3;
        }
    s0 += __shfl_xor_sync(0xffffffffu, s0, 1);
    s0 += __shfl_xor_sync(0xffffffffu, s0, 2);
    s1 += __shfl_xor_sync(0xffffffffu, s1, 1);
    s1 += __shfl_xor_sync(0xffffffffu, s1, 2);
    if (q == 0) {
        red[256 + r0 * 4 + (wid & 3)] = s0;
        red[256 + r1 * 4 + (wid & 3)] = s1;
    }
    __syncthreads();
    float inv0 = 1.0f / (red[256 + r0 * 4 + 0] + red[256 + r0 * 4 + 1] +
                         red[256 + r0 * 4 + 2] + red[256 + r0 * 4 + 3]);
    float inv1 = 1.0f / (red[256 + r1 * 4 + 0] + red[256 + r1 * 4 + 1] +
                         red[256 + r1 * 4 + 2] + red[256 + r1 * 4 + 3]);

    // write att fp32 (streaming) + att bf16 (cached, re-read by gemm_av)
    const size_t arow = ((size_t)b * NH + h) * NUMS;
    float* a0 = att_out + (arow + n0 + r0) * NUMS;
    float* a1 = att_out + (arow + n0 + r1) * NUMS;
    __nv_bfloat16* ab0 = g_attb + (arow + n0 + r0) * NUMS;
    __nv_bfloat16* ab1 = g_attb + (arow + n0 + r1) * NUMS;
#pragma unroll
    for (int ck = 0; ck < 8; ck++)
#pragma unroll
        for (int nt = 0; nt < 2; nt++) {
            const int col = ck * 64 + wn2 + nt * 8 + q * 2;
            float p0 = cA[ck][nt][0] * inv0, p1 = cA[ck][nt][1] * inv0;
            float p2 = cA[ck][nt][2] * inv1, p3 = cA[ck][nt][3] * inv1;
            __stcs((float2*)&a0[col], make_float2(p0, p1));
            __stcs((float2*)&a1[col], make_float2(p2, p3));
            *(uint32_t*)&ab0[col] = pack2(p0, p1);
            *(uint32_t*)&ab1[col] = pack2(p2, p3);
        }
}

// ----------------------------------------------------------------
extern "C" void kernel_launch(void* const* d_in, const int* in_sizes, int n_in,
                              void* d_out, int out_size) {
    const float*    x1   = (const float*)d_in[0];
    const float*    x2   = (const float*)d_in[1];
    const unsigned* mask = (const unsigned*)d_in[4];
    const float*    Wq   = (const float*)d_in[5];
    const float*    bq   = (const float*)d_in[6];
    const float*    Wl   = (const float*)d_in[7];
    const float*    bl   = (const float*)d_in[8];
    float* out = (float*)d_out;
    float* att = out + (size_t)BSZ * NUMS * FEAT;   // tuple: (xout, att)

    dim3 gg(FEAT / 256, BSZ);
    gate_kernel<<<gg, 256>>>(x2);

    { void* p; cudaGetSymbolAddress(&p, g_x1h);
      cvt_h<<<(int)(NF / 4 / 256), 256>>>(x1, (__nv_bfloat16*)p, (int)(NF / 4)); }
    { void* p; cudaGetSymbolAddress(&p, g_Wqh);
      cvt_h<<<FEAT * FEAT / 4 / 256, 256>>>(Wq, (__nv_bfloat16*)p, FEAT * FEAT / 4); }
    { void* p; cudaGetSymbolAddress(&p, g_Wlh);
      cvt_h<<<FEAT * FEAT / 4 / 256, 256>>>(Wl, (__nv_bfloat16*)p, FEAT * FEAT / 4); }

    mask_pack<<<BSZ * NUMS * NUMS / 256, 256>>>(mask);

    cudaFuncSetAttribute(gemm_mma<0>, cudaFuncAttributeMaxDynamicSharedMemorySize, GEMM_SMEM);
    cudaFuncSetAttribute(gemm_mma<1>, cudaFuncAttributeMaxDynamicSharedMemorySize, GEMM_SMEM);
    cudaFuncSetAttribute(gemm_av,     cudaFuncAttributeMaxDynamicSharedMemorySize, GEMM_SMEM);
    cudaFuncSetAttribute(attn_s,      cudaFuncAttributeMaxDynamicSharedMemorySize, ATT_SMEM);

    dim3 ggemm(FEAT / 128, (BSZ * NUMS) / 128);
    gemm_mma<0><<<ggemm, 512, GEMM_SMEM>>>(bq, nullptr, nullptr);

    dim3 ga(NUMS / 64, NH, BSZ);
    attn_s<<<ga, 512, ATT_SMEM>>>(att);

    dim3 gav(NUMS / 128, NH, BSZ);
    gemm_av<<<gav, 512, GEMM_SMEM>>>();

    gemm_mma<1><<<ggemm, 512, GEMM_SMEM>>>(bl, x1, out);
}

// round 15
// speedup vs baseline: 1.1587x; 1.1003x over previous
#include <cuda_runtime.h>
#include <cuda_bf16.h>
#include <cstdint>

#define BSZ  32
#define NUMS 512
#define FEAT 1024
#define NH   8
#define HLEN 128

#define NF ((size_t)BSZ * NUMS * FEAT)
// bf16 scratch (allocation-free rule: __device__ globals)
__device__ __nv_bfloat16 g_x1h[NF];                 // x1 bf16, [b,n,f]
__device__ __nv_bfloat16 g_Qh [NF];                 // Q*(gate^2*scale) bf16, [b,h,n,d]
__device__ __nv_bfloat16 g_Oh [NF];                 // att@V bf16, [b,n,f]
__device__ __nv_bfloat16 g_Wqh[FEAT * FEAT];        // [h,f,d] flat
__device__ __nv_bfloat16 g_Wlh[FEAT * FEAT];        // [f,n]
__device__ float g_gate2[BSZ * FEAT];
__device__ uint32_t g_mbits[BSZ * NUMS * (NUMS / 32)];   // packed mask bits

// ---------------------------------------------------------------- helpers
__device__ __forceinline__ uint32_t smem_u32(const void* p) {
    uint32_t a;
    asm("{ .reg .u64 t; cvta.to.shared.u64 t, %1; cvt.u32.u64 %0, t; }" : "=r"(a) : "l"(p));
    return a;
}
__device__ __forceinline__ uint32_t pack2(float a, float b) {
    __nv_bfloat162 t = __floats2bfloat162_rn(a, b);
    return *(uint32_t*)&t;
}
__device__ __forceinline__ void mma16816(float* c, const uint32_t* a, const uint32_t* b) {
    asm volatile(
        "mma.sync.aligned.m16n8k16.row.col.f32.bf16.bf16.f32 "
        "{%0,%1,%2,%3}, {%4,%5,%6,%7}, {%8,%9}, {%0,%1,%2,%3};"
        : "+f"(c[0]), "+f"(c[1]), "+f"(c[2]), "+f"(c[3])
        : "r"(a[0]), "r"(a[1]), "r"(a[2]), "r"(a[3]), "r"(b[0]), "r"(b[1]));
}
__device__ __forceinline__ void ldm_x4(uint32_t* r, uint32_t sa) {
    asm volatile("ldmatrix.sync.aligned.m8n8.x4.shared.b16 {%0,%1,%2,%3}, [%4];"
        : "=r"(r[0]), "=r"(r[1]), "=r"(r[2]), "=r"(r[3]) : "r"(sa));
}
__device__ __forceinline__ void ldm_x4_t(uint32_t* r, uint32_t sa) {
    asm volatile("ldmatrix.sync.aligned.m8n8.x4.trans.shared.b16 {%0,%1,%2,%3}, [%4];"
        : "=r"(r[0]), "=r"(r[1]), "=r"(r[2]), "=r"(r[3]) : "r"(sa));
}
__device__ __forceinline__ void cpa16(uint32_t dst, const void* src) {
    asm volatile("cp.async.cg.shared.global [%0], [%1], 16;" :: "r"(dst), "l"(src));
}
#define CP_COMMIT() asm volatile("cp.async.commit_group;" ::: "memory")
#define CP_WAIT(n)  asm volatile("cp.async.wait_group %0;" :: "n"(n) : "memory")

// ---------------------------------------------------------------- fused convert
// covers x1 (NF/4 quads), then Wq, then Wl (FEAT*FEAT/4 each)
__global__ void cvt_all(const float* __restrict__ x1, const float* __restrict__ Wq,
                        const float* __restrict__ Wl) {
    const int NQ1 = (int)(NF / 4);
    const int NQW = FEAT * FEAT / 4;
    int i = blockIdx.x * 256 + threadIdx.x;
    const float* src;
    __nv_bfloat16* dst;
    int j;
    if (i < NQ1) { src = x1; dst = g_x1h; j = i; }
    else if (i < NQ1 + NQW) { src = Wq; dst = g_Wqh; j = i - NQ1; }
    else if (i < NQ1 + 2 * NQW) { src = Wl; dst = g_Wlh; j = i - NQ1 - NQW; }
    else return;
    float4 v = ((const float4*)src)[j];
    ((uint2*)dst)[j] = make_uint2(pack2(v.x, v.y), pack2(v.z, v.w));
}

// ---------------------------------------------------------------- pack mask -> bits
__global__ void mask_pack(const unsigned* __restrict__ mask) {
    int t = blockIdx.x * 256 + threadIdx.x;
    unsigned v = mask[t];
    uint32_t w = __ballot_sync(0xffffffffu, v != 0);
    if ((t & 31) == 0) g_mbits[t >> 5] = w;
}

// ---------------------------------------------------------------- gate^2
__global__ void gate_kernel(const float* __restrict__ x2) {
    int b = blockIdx.y;
    int f = blockIdx.x * 256 + threadIdx.x;
    const float* p = x2 + (size_t)b * NUMS * FEAT + f;
    float s = 0.f;
#pragma unroll 8
    for (int n = 0; n < NUMS; n++) s += p[(size_t)n * FEAT];
    float g = s * (1.0f / NUMS);
    g_gate2[b * FEAT + f] = g * g * 0.08838834764831845f;  // 1/sqrt(128)
}

// ================================================================
// pipelined bf16 GEMM (at mma.sync floor): k-chunk 64, 3 stages.
#define AELE 9216
#define BELE 8704
#define STAGE_E (AELE + BELE)
#define GEMM_SMEM (3 * STAGE_E * 2)         // 107520 B

template <int MODE>
__global__ void __launch_bounds__(512) gemm_mma(
    const float* __restrict__ bias, const float* __restrict__ res,
    float* __restrict__ Cout)
{
    extern __shared__ __nv_bfloat16 smb[];
    const uint32_t sb = smem_u32(smb);
    const int tid = threadIdx.x;
    const int n0 = blockIdx.x * 128;
    const int m0 = blockIdx.y * 128;
    const int wid = tid >> 5, lane = tid & 31;
    const int wm = (wid >> 2) * 32, wn = (wid & 3) * 32;
    const int g = lane >> 2, q = lane & 3;

    const __nv_bfloat16* Ahg = MODE ? g_Oh : g_x1h;
    const __nv_bfloat16* Bhg = MODE ? g_Wlh + n0 : g_Wqh + (size_t)(n0 >> 7) * FEAT * HLEN;
    const int ldbn = MODE ? FEAT : HLEN;

    const int ar = tid >> 2, ac = (tid & 3) * 16;
    const int br = tid >> 3, bc = (tid & 7) * 16;
    const size_t aoff = (size_t)(m0 + ar) * FEAT + ac;

    auto issue = [&](int slot, int k0) {
        uint32_t s = sb + slot * STAGE_E * 2;
        const __nv_bfloat16* ap = Ahg + aoff + k0;
        uint32_t da = s + (ar * 72 + ac) * 2;
        cpa16(da,      ap);
        cpa16(da + 16, ap + 8);
        const __nv_bfloat16* bp = Bhg + (size_t)(k0 + br) * ldbn + bc;
        uint32_t db = s + AELE * 2 + (br * 136 + bc) * 2;
        cpa16(db,      bp);
        cpa16(db + 16, bp + 8);
        CP_COMMIT();
    };

    float c[2][4][4];
#pragma unroll
    for (int i = 0; i < 2; i++)
#pragma unroll
        for (int j = 0; j < 4; j++)
#pragma unroll
            for (int k = 0; k < 4; k++) c[i][j][k] = 0.f;

    const uint32_t lnA = ((lane & 15) * 72 + (lane >> 4) * 8) * 2;
    const uint32_t lnB = ((lane & 15) * 136 + (lane >> 4) * 8) * 2;

    issue(0, 0);
    issue(1, 64);

    for (int ch = 0; ch < 16; ch++) {
        if (ch < 15) { CP_WAIT(1); } else { CP_WAIT(0); }
        __syncthreads();
        if (ch + 2 <= 15) issue((ch + 2) % 3, (ch + 2) * 64);

        uint32_t sA = sb + (ch % 3) * STAGE_E * 2;
        uint32_t sB = sA + AELE * 2;
#pragma unroll
        for (int ks = 0; ks < 4; ks++) {
            uint32_t ah[2][4];
#pragma unroll
            for (int mt = 0; mt < 2; mt++)
                ldm_x4(ah[mt], sA + ((wm + mt * 16) * 72 + ks * 16) * 2 + lnA);
            uint32_t bfh[2][4];
#pragma unroll
            for (int bg = 0; bg < 2; bg++)
                ldm_x4_t(bfh[bg], sB + (ks * 16 * 136 + wn + bg * 16) * 2 + lnB);
#pragma unroll
            for (int mt = 0; mt < 2; mt++)
#pragma unroll
                for (int nt = 0; nt < 4; nt++)
                    mma16816(c[mt][nt], ah[mt], &bfh[nt >> 1][(nt & 1) * 2]);
        }
    }

#pragma unroll
    for (int mt = 0; mt < 2; mt++)
#pragma unroll
        for (int nt = 0; nt < 4; nt++) {
            const int dcol = wn + nt * 8 + q * 2;
            const int col = n0 + dcol;
#pragma unroll
            for (int hh = 0; hh < 2; hh++) {
                const int m = m0 + wm + mt * 16 + g + hh * 8;
                float v0 = c[mt][nt][hh * 2 + 0];
                float v1 = c[mt][nt][hh * 2 + 1];
                if (MODE == 0) {
                    const int bi = m >> 9, ns = m & 511, h = n0 >> 7;
                    v0 = (v0 + bias[col])     * g_gate2[bi * FEAT + col];
                    v1 = (v1 + bias[col + 1]) * g_gate2[bi * FEAT + col + 1];
                    size_t o = (((size_t)bi * NH + h) * NUMS + ns) * HLEN + dcol;
                    *(uint32_t*)&g_Qh[o] = pack2(v0, v1);
                } else {
                    float2 o;
                    o.x = fmaxf(v0 + bias[col], 0.f)     + res[(size_t)m * FEAT + col];
                    o.y = fmaxf(v1 + bias[col + 1], 0.f) + res[(size_t)m * FEAT + col + 1];
                    *(float2*)&Cout[(size_t)m * FEAT + col] = o;
                }
            }
        }
}

// ================================================================
// attention (R12 base): register S/softmax, 8 resident K-chunks, bitmask;
// R15 change: Q fragments hoisted to registers once.
// smem: Q[64][136] bf16 @0 (17408); P[64][520] bf16 @17408 (66560);
//       KV 8 slots @83968 (8x17408=139264); redbuf @223232 (2048). total 225280.
#define QOFF 0
#define POFF 17408
#define KVOFF 83968
#define REDOFF 223232
#define ATT_SMEM 225280
__global__ void __launch_bounds__(512) attn_mma(float* __restrict__ att_out)
{
    extern __shared__ char smc[];
    const uint32_t sb = smem_u32(smc);
    float* red = (float*)(smc + REDOFF);
    const int tid = threadIdx.x;
    const int wid = tid >> 5, lane = tid & 31;
    const int g = lane >> 2, q = lane & 3;
    const int n0 = blockIdx.x * 64;
    const int h = blockIdx.y, b = blockIdx.z;

    const uint32_t lnB = ((lane & 15) * 136 + (lane >> 4) * 8) * 2;
    const uint32_t KVB = sb + KVOFF;
    const uint32_t PB  = sb + POFF;

    auto issueKV = [&](int ck) {
        const int row = tid >> 3, cb = (tid & 7) * 16;
        size_t so = ((size_t)b * NUMS + ck * 64 + row) * FEAT + h * HLEN + cb;
        uint32_t d = KVB + ck * 17408 + (row * 136 + cb) * 2;
        cpa16(d,      g_x1h + so);
        cpa16(d + 16, g_x1h + so + 8);
        CP_COMMIT();
    };

    // ---- prologue: Q, then K chunks 0,1
    {
        const int row = tid >> 3, cb = (tid & 7) * 16;
        size_t so = (((size_t)b * NH + h) * NUMS + n0 + row) * HLEN + cb;
        uint32_t d = sb + QOFF + (row * 136 + cb) * 2;
        cpa16(d,      g_Qh + so);
        cpa16(d + 16, g_Qh + so + 8);
        CP_COMMIT();
    }
    issueKV(0);
    issueKV(1);

    const int wm2 = (wid >> 2) * 16, wn2 = (wid & 3) * 16;
    const int r0 = wm2 + g, r1 = r0 + 8;
    const uint32_t* mb0 = g_mbits + ((size_t)b * NUMS + n0 + r0) * (NUMS / 32);
    const uint32_t* mb1 = g_mbits + ((size_t)b * NUMS + n0 + r1) * (NUMS / 32);

    // Q + K0 resident; hoist Q fragments once
    CP_WAIT(1);
    __syncthreads();
    uint32_t qf[8][4];
#pragma unroll
    for (int ks = 0; ks < 8; ks++)
        ldm_x4(qf[ks], sb + QOFF + (wm2 * 136 + ks * 16) * 2 + lnB);

    // S fragments: [chunk][nt][4]
    float cA[8][2][4];

    // ---- phase 1: S = Q K^T, 8 chunks of 64 keys into distinct slots
#pragma unroll
    for (int ck = 0; ck < 8; ck++) {
        if (ck > 0) {
            if (ck < 7) { CP_WAIT(1); } else { CP_WAIT(0); }
            __syncthreads();
        }
        if (ck + 2 <= 7) issueKV(ck + 2);

        uint32_t kbh = KVB + ck * 17408;
        float* c0 = cA[ck][0];
        float* c1 = cA[ck][1];
#pragma unroll
        for (int k = 0; k < 4; k++) { c0[k] = 0.f; c1[k] = 0.f; }
#pragma unroll
        for (int ks = 0; ks < 8; ks++) {
            uint32_t kh[4];
            ldm_x4(kh, kbh + (wn2 * 136 + ks * 16) * 2 + lnB);
            uint32_t b0h[2] = {kh[0], kh[2]}, b1h[2] = {kh[1], kh[3]};
            mma16816(c0, qf[ks], b0h);
            mma16816(c1, qf[ks], b1h);
        }
        // fold mask from packed bits (register-resident)
#pragma unroll
        for (int nt = 0; nt < 2; nt++) {
            const int col = ck * 64 + wn2 + nt * 8 + q * 2;
            uint32_t w0 = (mb0[col >> 5] >> (col & 31)) & 3u;
            uint32_t w1 = (mb1[col >> 5] >> (col & 31)) & 3u;
            if (w0 & 1u) cA[ck][nt][0] = -1e9f;
            if (w0 & 2u) cA[ck][nt][1] = -1e9f;
            if (w1 & 1u) cA[ck][nt][2] = -1e9f;
            if (w1 & 2u) cA[ck][nt][3] = -1e9f;
        }
    }

    // ---- phase 2: register softmax (quad shfl + cross-warp smem reduce)
    float mx0 = -1e30f, mx1 = -1e30f;
#pragma unroll
    for (int ck = 0; ck < 8; ck++)
#pragma unroll
        for (int nt = 0; nt < 2; nt++) {
            mx0 = fmaxf(mx0, fmaxf(cA[ck][nt][0], cA[ck][nt][1]));
            mx1 = fmaxf(mx1, fmaxf(cA[ck][nt][2], cA[ck][nt][3]));
        }
    mx0 = fmaxf(mx0, __shfl_xor_sync(0xffffffffu, mx0, 1));
    mx0 = fmaxf(mx0, __shfl_xor_sync(0xffffffffu, mx0, 2));
    mx1 = fmaxf(mx1, __shfl_xor_sync(0xffffffffu, mx1, 1));
    mx1 = fmaxf(mx1, __shfl_xor_sync(0xffffffffu, mx1, 2));
    if (q == 0) {
        red[r0 * 4 + (wid & 3)] = mx0;
        red[r1 * 4 + (wid & 3)] = mx1;
    }
    __syncthreads();
    mx0 = fmaxf(fmaxf(red[r0 * 4 + 0], red[r0 * 4 + 1]),
                fmaxf(red[r0 * 4 + 2], red[r0 * 4 + 3]));
    mx1 = fmaxf(fmaxf(red[r1 * 4 + 0], red[r1 * 4 + 1]),
                fmaxf(red[r1 * 4 + 2], red[r1 * 4 + 3]));

    float s0 = 0.f, s1 = 0.f;
#pragma unroll
    for (int ck = 0; ck < 8; ck++)
#pragma unroll
        for (int nt = 0; nt < 2; nt++) {
            float e0 = __expf(cA[ck][nt][0] - mx0);
            float e1 = __expf(cA[ck][nt][1] - mx0);
            float e2 = __expf(cA[ck][nt][2] - mx1);
            float e3 = __expf(cA[ck][nt][3] - mx1);
            cA[ck][nt][0] = e0; cA[ck][nt][1] = e1;
            cA[ck][nt][2] = e2; cA[ck][nt][3] = e3;
            s0 += e0 + e1; s1 += e2 + e3;
        }
    s0 += __shfl_xor_sync(0xffffffffu, s0, 1);
    s0 += __shfl_xor_sync(0xffffffffu, s0, 2);
    s1 += __shfl_xor_sync(0xffffffffu, s1, 1);
    s1 += __shfl_xor_sync(0xffffffffu, s1, 2);
    if (q == 0) {
        red[256 + r0 * 4 + (wid & 3)] = s0;
        red[256 + r1 * 4 + (wid & 3)] = s1;
    }
    __syncthreads();
    float inv0 = 1.0f / (red[256 + r0 * 4 + 0] + red[256 + r0 * 4 + 1] +
                         red[256 + r0 * 4 + 2] + red[256 + r0 * 4 + 3]);
    float inv1 = 1.0f / (red[256 + r1 * 4 + 0] + red[256 + r1 * 4 + 1] +
                         red[256 + r1 * 4 + 2] + red[256 + r1 * 4 + 3]);

    // write att (fp32, streaming) + P (bf16, smem)
    float* arow0 = att_out + (((size_t)b * NH + h) * NUMS + (n0 + r0)) * NUMS;
    float* arow1 = att_out + (((size_t)b * NH + h) * NUMS + (n0 + r1)) * NUMS;
#pragma unroll
    for (int ck = 0; ck < 8; ck++)
#pragma unroll
        for (int nt = 0; nt < 2; nt++) {
            const int col = ck * 64 + wn2 + nt * 8 + q * 2;
            float p0 = cA[ck][nt][0] * inv0, p1 = cA[ck][nt][1] * inv0;
            float p2 = cA[ck][nt][2] * inv1, p3 = cA[ck][nt][3] * inv1;
            __stcs((float2*)&arow0[col], make_float2(p0, p1));
            __stcs((float2*)&arow1[col], make_float2(p2, p3));
            *(uint32_t*)(smc + POFF + (r0 * 520 + col) * 2) = pack2(p0, p1);
            *(uint32_t*)(smc + POFF + (r1 * 520 + col) * 2) = pack2(p2, p3);
        }
    __syncthreads();                 // P complete

    // ---- phase 3: O = att @ V — V chunks already resident; pure compute
    const int wm3 = (wid >> 2) * 16, wn3 = (wid & 3) * 32;
    const uint32_t lnP = ((lane & 15) * 520 + (lane >> 4) * 8) * 2;
    float c3[4][4];
#pragma unroll
    for (int i = 0; i < 4; i++)
#pragma unroll
        for (int k = 0; k < 4; k++) c3[i][k] = 0.f;

    for (int kt = 0; kt < 8; kt++) {
        uint32_t vbh = KVB + kt * 17408;
#pragma unroll
        for (int ks = 0; ks < 4; ks++) {
            uint32_t ph[4];
            ldm_x4(ph, PB + (wm3 * 520 + kt * 64 + ks * 16) * 2 + lnP);
#pragma unroll
            for (int vg = 0; vg < 2; vg++) {
                uint32_t vh[4];
                ldm_x4_t(vh, vbh + (ks * 16 * 136 + wn3 + vg * 16) * 2 + lnB);
                mma16816(c3[vg * 2 + 0], ph, &vh[0]);
                mma16816(c3[vg * 2 + 1], ph, &vh[2]);
            }
        }
    }

    // ---- epilogue: O -> g_Oh [b, n, f] (bf16)
#pragma unroll
    for (int vg = 0; vg < 2; vg++)
#pragma unroll
        for (int hf = 0; hf < 2; hf++) {
            const float* cc = c3[vg * 2 + hf];
            const int d = wn3 + vg * 16 + hf * 8 + q * 2;
            const int row = wm3 + g;
            size_t o0 = ((size_t)b * NUMS + n0 + row) * FEAT + h * HLEN + d;
            size_t o1 = o0 + 8 * FEAT;
            *(uint32_t*)&g_Oh[o0] = pack2(cc[0], cc[1]);
            *(uint32_t*)&g_Oh[o1] = pack2(cc[2], cc[3]);
        }
}

// ----------------------------------------------------------------
extern "C" void kernel_launch(void* const* d_in, const int* in_sizes, int n_in,
                              void* d_out, int out_size) {
    const float*    x1   = (const float*)d_in[0];
    const float*    x2   = (const float*)d_in[1];
    const unsigned* mask = (const unsigned*)d_in[4];
    const float*    Wq   = (const float*)d_in[5];
    const float*    bq   = (const float*)d_in[6];
    const float*    Wl   = (const float*)d_in[7];
    const float*    bl   = (const float*)d_in[8];
    float* out = (float*)d_out;
    float* att = out + (size_t)BSZ * NUMS * FEAT;   // tuple: (xout, att)

    dim3 gg(FEAT / 256, BSZ);
    gate_kernel<<<gg, 256>>>(x2);

    const int CVT_QUADS = (int)(NF / 4) + 2 * (FEAT * FEAT / 4);
    cvt_all<<<(CVT_QUADS + 255) / 256, 256>>>(x1, Wq, Wl);

    mask_pack<<<BSZ * NUMS * NUMS / 256, 256>>>(mask);

    cudaFuncSetAttribute(gemm_mma<0>, cudaFuncAttributeMaxDynamicSharedMemorySize, GEMM_SMEM);
    cudaFuncSetAttribute(gemm_mma<1>, cudaFuncAttributeMaxDynamicSharedMemorySize, GEMM_SMEM);
    cudaFuncSetAttribute(attn_mma,    cudaFuncAttributeMaxDynamicSharedMemorySize, ATT_SMEM);

    dim3 ggemm(FEAT / 128, (BSZ * NUMS) / 128);
    gemm_mma<0><<<ggemm, 512, GEMM_SMEM>>>(bq, nullptr, nullptr);

    dim3 ga(NUMS / 64, NH, BSZ);
    attn_mma<<<ga, 512, ATT_SMEM>>>(att);

    gemm_mma<1><<<ggemm, 512, GEMM_SMEM>>>(bl, x1, out);
}